// round 4
// baseline (speedup 1.0000x reference)
#include <cuda_runtime.h>
#include <cstddef>

#define Tn 10
#define Bn 4
#define Cc 64
#define Hh 64
#define Ww 64
#define HWp 4096
#define TH 8                  // tile rows
#define TW 16                 // tile cols
#define RS 20                 // smem row stride (floats)
#define ICS 200               // 10 halo rows * RS
#define SM_IN (64*ICS)        // 12800 floats
#define SW_A (8*32*12)        // 3072 floats
#define SW_B (8*16*12)        // 1536 floats
#define SMEM_A ((SM_IN + SW_A)*4)   // 63488 B
#define SMEM_B ((SM_IN + SW_B)*4)   // 57344 B

// Recurrent state + inter-kernel scratch (allocation-free device globals)
__device__ float g_prev_y [Bn*Cc*HWp];
__device__ float g_h      [Bn*Cc*HWp];
__device__ float g_gate_in[Bn*Cc*HWp];
__device__ float g_upd    [Bn*Cc*HWp];
__device__ float g_thr    [Bn*HWp];

__device__ __forceinline__ float sigmoidf_(float x) { return 1.0f / (1.0f + __expf(-x)); }

// 10x18 halo tile, all 64 input channels, zero-padded SAME
__device__ __forceinline__ void load_tile(const float* __restrict__ in, int b,
                                          int ty0, int tx0, float* s_in, int tid)
{
    for (int idx = tid; idx < 64 * 180; idx += 128) {
        int ic  = idx / 180;
        int rem = idx - ic * 180;
        int r   = rem / 18;
        int cc  = rem - r * 18;
        int gy  = ty0 + r - 1;
        int gx  = tx0 + cc - 1;
        float v = 0.0f;
        if (gy >= 0 && gy < Hh && gx >= 0 && gx < Ww)
            v = in[((b * Cc + ic) * Hh + gy) * Ww + gx];
        s_in[ic * ICS + r * RS + cc] = v;
    }
}

// Stage weights: s_w[icl][ocl][12] row-stride 12
template<int NOC>
__device__ __forceinline__ void stage_w(const float* __restrict__ w, int oc_base,
                                        int cc0, float* s_w, int tid)
{
    for (int i = tid; i < 8 * NOC * 9; i += 128) {
        int icl = i / (NOC * 9);
        int rem = i - icl * (NOC * 9);
        int oc  = rem / 9;
        int tap = rem - oc * 9;
        s_w[icl * (NOC * 12) + oc * 12 + tap] =
            w[(oc_base + oc) * 576 + (cc0 + icl) * 9 + tap];
    }
}

// Inner MAC over one 8-ic chunk: KOC ocs x 3x3 x 4 px
template<int NOC, int KOC>
__device__ __forceinline__ void mac_chunk(const float* s_in, const float* s_w,
                                          int cc0, int py, int xb, int ocq,
                                          float acc[KOC][4])
{
    #pragma unroll
    for (int icl = 0; icl < 8; icl++) {
        const float* sin = s_in + (cc0 + icl) * ICS + py * RS + xb;
        float x[3][8];
        #pragma unroll
        for (int dy = 0; dy < 3; dy++) {
            float4 a  = *(const float4*)(sin + dy * RS);
            float4 b4 = *(const float4*)(sin + dy * RS + 4);
            x[dy][0]=a.x;  x[dy][1]=a.y;  x[dy][2]=a.z;  x[dy][3]=a.w;
            x[dy][4]=b4.x; x[dy][5]=b4.y; x[dy][6]=b4.z; x[dy][7]=b4.w;
        }
        const float* sw = s_w + icl * (NOC * 12) + (ocq * KOC) * 12;
        #pragma unroll
        for (int k = 0; k < KOC; k++) {
            float4 w0 = *(const float4*)(sw + k * 12);
            float4 w1 = *(const float4*)(sw + k * 12 + 4);
            float  w8 = sw[k * 12 + 8];
            float wv[9] = {w0.x, w0.y, w0.z, w0.w, w1.x, w1.y, w1.z, w1.w, w8};
            #pragma unroll
            for (int dy = 0; dy < 3; dy++)
                #pragma unroll
                for (int dx = 0; dx < 3; dx++) {
                    float wt = wv[dy * 3 + dx];
                    #pragma unroll
                    for (int p = 0; p < 4; p++)
                        acc[k][p] += wt * x[dy][dx + p];
                }
        }
    }
}

// ---------------------------------------------------------------------------
// Kernel A: rz = conv3x3(prev_y, w_rz)+b_rz; gates; thr channel in grp 0
// grid (32 tiles 16x8, 4 grp x 32oc, 4 b) = 512 blocks, 128 threads
// ---------------------------------------------------------------------------
__global__ void __launch_bounds__(128)
kA(const float* __restrict__ xt, const float* __restrict__ w_rz,
   const float* __restrict__ b_rz, int t)
{
    extern __shared__ float smem[];
    float* s_in = smem;
    float* s_w  = smem + SM_IN;

    const int tid  = threadIdx.x;
    const int tile = blockIdx.x;        // 0..31
    const int grp  = blockIdx.y;        // 0..3
    const int b    = blockIdx.z;
    const int ty0  = (tile >> 2) * TH;
    const int tx0  = (tile & 3) * TW;

    if (t > 0) load_tile(g_prev_y, b, ty0, tx0, s_in, tid);

    const int oc_base = grp * 32;
    const int ocq = tid >> 5;           // 0..3 (warp-uniform)
    const int pg  = tid & 31;
    const int py  = pg >> 2;            // 0..7
    const int xb  = (pg & 3) * 4;       // 0,4,8,12

    float acc[8][4];
    #pragma unroll
    for (int k = 0; k < 8; k++)
        #pragma unroll
        for (int p = 0; p < 4; p++) acc[k][p] = 0.0f;

    if (t > 0) {
        for (int cc0 = 0; cc0 < 64; cc0 += 8) {
            __syncthreads();
            stage_w<32>(w_rz, oc_base, cc0, s_w, tid);
            __syncthreads();
            mac_chunk<32, 8>(s_in, s_w, cc0, py, xb, ocq, acc);
        }
    }

    // Epilogue: gates (grp 0,1 -> z/update; grp 2,3 -> r/reset)
    const int gy   = ty0 + py;
    const int pix0 = gy * Ww + tx0 + xb;
    #pragma unroll
    for (int k = 0; k < 8; k++) {
        int oc = oc_base + ocq * 8 + k;
        float bias = b_rz[oc];
        float4 xi = *(const float4*)&xt[((((size_t)t * Bn + b) * 192) + oc) * HWp + pix0];
        float4 sg;
        sg.x = sigmoidf_(acc[k][0] + bias + xi.x);
        sg.y = sigmoidf_(acc[k][1] + bias + xi.y);
        sg.z = sigmoidf_(acc[k][2] + bias + xi.z);
        sg.w = sigmoidf_(acc[k][3] + bias + xi.w);
        if (grp < 2) {
            *(float4*)&g_upd[(size_t)(b * Cc + oc) * HWp + pix0] = sg;
        } else {
            int c = oc - 64;
            float4 g = {0.f, 0.f, 0.f, 0.f};
            if (t > 0) {
                const float* sp = s_in + c * ICS + (py + 1) * RS + xb + 1;
                g.x = sp[0] * sg.x; g.y = sp[1] * sg.y;
                g.z = sp[2] * sg.z; g.w = sp[3] * sg.w;
            }
            *(float4*)&g_gate_in[(size_t)(b * Cc + c) * HWp + pix0] = g;
        }
    }

    // Threshold channel (oc 128), grp 0 only: 128 px, 1 px/thread
    if (grp == 0) {
        const int px1 = tid & 15, py1 = tid >> 4;   // 16x8
        float accT = 0.0f;
        if (t > 0) {
            __syncthreads();
            for (int i = tid; i < 576; i += 128)
                s_w[i] = w_rz[128 * 576 + i];
            __syncthreads();
            float a0 = 0.f, a1 = 0.f, a2 = 0.f;
            for (int ic = 0; ic < 64; ic++) {
                const float* sin = s_in + ic * ICS + py1 * RS + px1;
                const float* sw  = s_w + ic * 9;
                a0 += sw[0]*sin[0]    + sw[3]*sin[RS]     + sw[6]*sin[2*RS];
                a1 += sw[1]*sin[1]    + sw[4]*sin[RS+1]   + sw[7]*sin[2*RS+1];
                a2 += sw[2]*sin[2]    + sw[5]*sin[RS+2]   + sw[8]*sin[2*RS+2];
            }
            accT = a0 + a1 + a2;
        }
        g_thr[b * HWp + (ty0 + py1) * Ww + (tx0 + px1)] = sigmoidf_(accT + b_rz[128]);
    }
}

// ---------------------------------------------------------------------------
// Kernel B: f = conv3x3(gate_in, w_f)+b_f+xi_f; GRU update + spike + outputs
// grid (32 tiles, 4 grp x 16oc, 4 b) = 512 blocks, 128 threads
// ---------------------------------------------------------------------------
__global__ void __launch_bounds__(128)
kB(const float* __restrict__ xt, const float* __restrict__ w_f,
   const float* __restrict__ b_f, float* __restrict__ out, int t)
{
    extern __shared__ float smem[];
    float* s_in = smem;
    float* s_w  = smem + SM_IN;

    const int tid  = threadIdx.x;
    const int tile = blockIdx.x;
    const int grp  = blockIdx.y;        // 0..3 (16 oc each)
    const int b    = blockIdx.z;
    const int ty0  = (tile >> 2) * TH;
    const int tx0  = (tile & 3) * TW;

    load_tile(g_gate_in, b, ty0, tx0, s_in, tid);

    const int oc_base = grp * 16;
    const int ocq = tid >> 5;           // 0..3
    const int pg  = tid & 31;
    const int py  = pg >> 2;
    const int xb  = (pg & 3) * 4;

    float acc[4][4];
    #pragma unroll
    for (int k = 0; k < 4; k++)
        #pragma unroll
        for (int p = 0; p < 4; p++) acc[k][p] = 0.0f;

    for (int cc0 = 0; cc0 < 64; cc0 += 8) {
        __syncthreads();
        stage_w<16>(w_f, oc_base, cc0, s_w, tid);
        __syncthreads();
        mac_chunk<16, 4>(s_in, s_w, cc0, py, xb, ocq, acc);
    }

    // Epilogue: GRU update + spike + outputs (vectorized)
    const size_t N = (size_t)Tn * Bn * Cc * HWp;
    const int gy   = ty0 + py;
    const int pix0 = gy * Ww + tx0 + xb;
    const float4 thr4 = *(const float4*)&g_thr[b * HWp + pix0];
    const float thrv[4] = {thr4.x, thr4.y, thr4.z, thr4.w};

    #pragma unroll
    for (int k = 0; k < 4; k++) {
        int oc = oc_base + ocq * 4 + k;
        float bias = b_f[oc];
        size_t sidx = (size_t)(b * Cc + oc) * HWp + pix0;
        float4 xi = *(const float4*)&xt[((((size_t)t * Bn + b) * 192) + 128 + oc) * HWp + pix0];
        float4 u4 = *(const float4*)&g_upd[sidx];
        float4 hp4 = {0.f,0.f,0.f,0.f};
        if (t > 0) hp4 = *(const float4*)&g_h[sidx];

        const float xiv[4] = {xi.x, xi.y, xi.z, xi.w};
        const float uv[4]  = {u4.x, u4.y, u4.z, u4.w};
        const float hpv[4] = {hp4.x, hp4.y, hp4.z, hp4.w};

        float4 yv, ev4, nd4, py4, hn4;
        float* yp  = &yv.x;  float* evp = &ev4.x;
        float* ndp = &nd4.x; float* hnp = &hn4.x;

        #pragma unroll
        for (int p = 0; p < 4; p++) {
            float f  = acc[k][p] + bias + xiv[p];
            float ig = tanhf(f);
            float h  = (1.0f - uv[p]) * hpv[p] + uv[p] * ig;
            float d  = h - thrv[p];
            float evt = (d > 0.0f) ? 1.0f : 0.0f;
            yp[p]  = evt * h;
            evp[p] = evt;
            ndp[p] = (d < 0.0f) ? (thrv[p] - h) : 0.0f;
            hnp[p] = h - evt * thrv[p];
        }
        py4 = yv;

        size_t o = (((size_t)t * Bn + b) * Cc + oc) * HWp + pix0;
        *(float4*)&out[o]         = yv;
        *(float4*)&out[N + o]     = ev4;
        *(float4*)&out[2 * N + o] = nd4;
        *(float4*)&g_prev_y[sidx] = py4;
        *(float4*)&g_h[sidx]      = hn4;
    }
}

extern "C" void kernel_launch(void* const* d_in, const int* in_sizes, int n_in,
                              void* d_out, int out_size)
{
    const float* xt   = (const float*)d_in[0];
    const float* w_rz = (const float*)d_in[1];
    const float* b_rz = (const float*)d_in[2];
    const float* w_f  = (const float*)d_in[3];
    const float* b_f  = (const float*)d_in[4];
    float* out = (float*)d_out;

    cudaFuncSetAttribute(kA, cudaFuncAttributeMaxDynamicSharedMemorySize, SMEM_A);
    cudaFuncSetAttribute(kB, cudaFuncAttributeMaxDynamicSharedMemorySize, SMEM_B);

    dim3 g(32, 4, Bn);
    for (int t = 0; t < Tn; t++) {
        kA<<<g, 128, SMEM_A>>>(xt, w_rz, b_rz, t);
        kB<<<g, 128, SMEM_B>>>(xt, w_f, b_f, out, t);
    }
}